// round 16
// baseline (speedup 1.0000x reference)
#include <cuda_runtime.h>
#include <cuda_bf16.h>
#include <cstdint>

#define N_ROWS   4096
#define N_FEAT   512
#define N_HID    64
#define N_CLASS  16
#define N_HEADS  8
#define PS       (N_ROWS + 4)
#define KR       (N_ROWS + 1)
#define NB       128            // mega-kernel grid size (all-resident)

// ---------------- scratch ----------------
__device__ __nv_bfloat16 g_xh [N_ROWS*N_FEAT];
__device__ __nv_bfloat16 g_xl [N_ROWS*N_FEAT];
__device__ __nv_bfloat16 g_whh[N_HEADS*N_FEAT*N_HID];
__device__ __nv_bfloat16 g_whl[N_HEADS*N_FEAT*N_HID];

__device__ float g_h1   [N_HEADS*N_ROWS*N_HID];
__device__ float g_ssrc1[N_HEADS*N_ROWS];
__device__ float g_sdst1[N_HEADS*N_ROWS];
__device__ float g_csort1[N_HEADS*N_ROWS];
__device__ float g_sorted1[N_HEADS*N_ROWS];
__device__ int   g_idx1 [N_HEADS*N_ROWS];
__device__ float g_Zhi1 [N_HEADS*PS];
__device__ float g_Zlo1 [N_HEADS*PS];
__device__ float g_Ze1  [N_HEADS*16];
__device__ float g_Zg1  [N_HEADS*16];
__device__ float g_Chi1 [N_HEADS*N_HID*16];
__device__ float g_Clo1 [N_HEADS*N_HID*16];
__device__ float g_Phi1 [N_HEADS*KR*N_HID];
__device__ float g_Plo1 [N_HEADS*KR*N_HID];
__device__ float g_xc   [N_ROWS*N_FEAT];

__device__ float g_h2   [N_ROWS*N_CLASS];
__device__ float g_ssrc2[N_ROWS];
__device__ float g_sdst2[N_ROWS];
__device__ float g_csort2[N_ROWS];
__device__ float g_sorted2[N_ROWS];
__device__ int   g_idx2 [N_ROWS];
__device__ float g_Zhi2 [PS];
__device__ float g_Zlo2 [PS];
__device__ float g_Ze2  [16];
__device__ float g_Zg2  [16];
__device__ float g_Chi2 [N_CLASS*16];
__device__ float g_Clo2 [N_CLASS*16];
__device__ float g_Phi2 [KR*N_CLASS];
__device__ float g_Plo2 [KR*N_CLASS];

// ---------------- device-wide software barrier ----------------
__device__ unsigned g_cnt;
__device__ volatile unsigned g_gen;

__device__ __forceinline__ void gbar() {
    __syncthreads();
    if (threadIdx.x == 0) {
        __threadfence();
        unsigned old = g_gen;
        if (atomicAdd(&g_cnt, 1u) == NB - 1) {
            g_cnt = 0;
            __threadfence();
            g_gen = old + 1;
        } else {
            while (g_gen == old) { __nanosleep(64); }
            __threadfence();
        }
    }
    __syncthreads();
}

// ---------------- S_a: sort one 512-chunk (descending), 1 elem/thread ----------------
__device__ void sortchunk_body(int h, int c, const float* __restrict__ sdst,
                               float* __restrict__ csort, float* sk)
{
    int tid = threadIdx.x;
    float key = 0.f;
    if (tid < 512) key = sdst[(size_t)h * N_ROWS + c * 512 + tid];
    for (int k = 2; k <= 512; k <<= 1) {
        for (int j = k >> 1; j > 0; j >>= 1) {
            if (j >= 32) {
                __syncthreads();
                if (tid < 512) sk[tid] = key;
                __syncthreads();
                if (tid < 512) {
                    float ok = sk[tid ^ j];
                    bool lower = (tid & j) == 0;
                    bool desc = ((tid & k & 511) == 0);
                    float a = lower ? key : ok, b = lower ? ok : key;
                    if (desc ? (a < b) : (a > b)) key = ok;
                }
            } else {
                if (tid < 512) {
                    float ok = __shfl_xor_sync(0xffffffffu, key, j);
                    bool lower = (tid & j) == 0;
                    bool desc = ((tid & k & 511) == 0);
                    float a = lower ? key : ok, b = lower ? ok : key;
                    if (desc ? (a < b) : (a > b)) key = ok;
                }
            }
        }
    }
    __syncthreads();
    if (tid < 512) csort[(size_t)h * N_ROWS + c * 512 + tid] = key;
}

// ---------------- S_b: rank own chunk + scatter sorted + idx recovery ----------------
__device__ void rank_body(int h, int c, const float* __restrict__ sdst,
                          const float* __restrict__ csort,
                          float* __restrict__ sorted, int* __restrict__ idx,
                          float* skeys, int* grank)
{
    int tid = threadIdx.x;
#pragma unroll
    for (int i = 0; i < 4; i++) skeys[tid + i * 1024] = csort[(size_t)h * N_ROWS + tid + i * 1024];
    __syncthreads();
    if (tid < 512) {
        float x = skeys[c * 512 + tid];
        int r = tid;
#pragma unroll
        for (int cc = 0; cc < 8; cc++) {
            if (cc == c) continue;
            const float* S = skeys + cc * 512;
            int lo = 0, hi = 512;
            if (cc < c) {
                while (lo < hi) { int mid = (lo + hi) >> 1; if (S[mid] >= x) lo = mid + 1; else hi = mid; }
            } else {
                while (lo < hi) { int mid = (lo + hi) >> 1; if (S[mid] > x) lo = mid + 1; else hi = mid; }
            }
            r += lo;
        }
        grank[tid] = r;
        sorted[(size_t)h * N_ROWS + r] = x;
    }
    __syncthreads();
    if (tid < 512) {
        int j = c * 512 + tid;
        float x = sdst[(size_t)h * N_ROWS + j];
        const float* S = skeys + c * 512;
        int lo = 0, hi = 512;
        while (lo < hi) { int mid = (lo + hi) >> 1; if (S[mid] > x) lo = mid + 1; else hi = mid; }
        int off = atomicAdd(&grank[lo], 0x10000) >> 16;
        int rank = grank[lo + off] & 0xFFFF;
        idx[(size_t)h * N_ROWS + rank] = j;
    }
    __syncthreads();
}

// ---------------- combined split fp32 -> bf16 hi/lo ----------------
#define NX4  (N_ROWS * N_FEAT / 4)
#define NW4  (N_HEADS * N_FEAT * N_HID / 4)
__global__ void splitall_kernel(const float* __restrict__ x, const float* __restrict__ Wh,
                                __nv_bfloat16* __restrict__ xh, __nv_bfloat16* __restrict__ xl,
                                __nv_bfloat16* __restrict__ whh, __nv_bfloat16* __restrict__ whl)
{
    int i = blockIdx.x * blockDim.x + threadIdx.x;
    const float* src; __nv_bfloat16 *hi, *lo; int j;
    if (i < NX4) { src = x; hi = xh; lo = xl; j = i; }
    else         { src = Wh; hi = whh; lo = whl; j = i - NX4; if (j >= NW4) return; }
    float4 v = reinterpret_cast<const float4*>(src)[j];
    __nv_bfloat16 h0 = __float2bfloat16_rn(v.x);
    __nv_bfloat16 h1 = __float2bfloat16_rn(v.y);
    __nv_bfloat16 h2 = __float2bfloat16_rn(v.z);
    __nv_bfloat16 h3 = __float2bfloat16_rn(v.w);
    __nv_bfloat16 l0 = __float2bfloat16_rn(v.x - __bfloat162float(h0));
    __nv_bfloat16 l1 = __float2bfloat16_rn(v.y - __bfloat162float(h1));
    __nv_bfloat16 l2 = __float2bfloat16_rn(v.z - __bfloat162float(h2));
    __nv_bfloat16 l3 = __float2bfloat16_rn(v.w - __bfloat162float(h3));
    __nv_bfloat162* hp = reinterpret_cast<__nv_bfloat162*>(hi) + j * 2;
    __nv_bfloat162* lp = reinterpret_cast<__nv_bfloat162*>(lo) + j * 2;
    hp[0] = __nv_bfloat162(h0, h1); hp[1] = __nv_bfloat162(h2, h3);
    lp[0] = __nv_bfloat162(l0, l1); lp[1] = __nv_bfloat162(l2, l3);
}

// ---------------- GEMM1 (bf16 mma + ldmatrix + fused scores) ----------------
__device__ __forceinline__ void mma16816(float* c, const uint32_t* a, const uint32_t* b) {
    asm volatile(
        "mma.sync.aligned.m16n8k16.row.col.f32.bf16.bf16.f32 "
        "{%0,%1,%2,%3}, {%4,%5,%6,%7}, {%8,%9}, {%0,%1,%2,%3};\n"
        : "+f"(c[0]), "+f"(c[1]), "+f"(c[2]), "+f"(c[3])
        : "r"(a[0]), "r"(a[1]), "r"(a[2]), "r"(a[3]), "r"(b[0]), "r"(b[1]));
}
__device__ __forceinline__ void ldmat_x4(uint32_t* r, uint32_t addr) {
    asm volatile("ldmatrix.sync.aligned.m8n8.x4.shared.b16 {%0,%1,%2,%3}, [%4];"
        : "=r"(r[0]), "=r"(r[1]), "=r"(r[2]), "=r"(r[3]) : "r"(addr));
}
__device__ __forceinline__ void ldmat_x4_t(uint32_t* r, uint32_t addr) {
    asm volatile("ldmatrix.sync.aligned.m8n8.x4.trans.shared.b16 {%0,%1,%2,%3}, [%4];"
        : "=r"(r[0]), "=r"(r[1]), "=r"(r[2]), "=r"(r[3]) : "r"(addr));
}

__global__ __launch_bounds__(256) void gemm1_mma_kernel(
    const __nv_bfloat16* __restrict__ xh, const __nv_bfloat16* __restrict__ xl,
    const __nv_bfloat16* __restrict__ whh, const __nv_bfloat16* __restrict__ whl,
    const float* __restrict__ ah,
    float* __restrict__ h1, float* __restrict__ ssrc, float* __restrict__ sdst)
{
    const int BM = 128, BKT = 64, SA = 72, SB = 72;
    __shared__ __nv_bfloat16 As[BM * SA];
    __shared__ __nv_bfloat16 Bs[BKT * SB];
    __shared__ float sred[2][2][BM];
    int h = blockIdx.y;
    int row0 = blockIdx.x * BM;
    int tid = threadIdx.x;
    int wid = tid >> 5, lane = tid & 31;
    int wm = wid & 3, wn = wid >> 2;
    int lr = lane >> 2, lc = lane & 3;
    int idx15 = lane & 15, hi8 = (lane >> 4) << 3;

    uint32_t sa_base = (uint32_t)__cvta_generic_to_shared(As);
    uint32_t sb_base = (uint32_t)__cvta_generic_to_shared(Bs);

    const __nv_bfloat16* Wb0 = whh + (size_t)h * N_FEAT * N_HID;
    const __nv_bfloat16* Wb1 = whl + (size_t)h * N_FEAT * N_HID;
    const __nv_bfloat16* Aph[3] = { xh, xl, xh };
    const __nv_bfloat16* Bph[3] = { Wb0, Wb0, Wb1 };

    float acc[2][4][4];
#pragma unroll
    for (int mm = 0; mm < 2; mm++)
#pragma unroll
        for (int nn = 0; nn < 4; nn++)
#pragma unroll
            for (int q = 0; q < 4; q++) acc[mm][nn][q] = 0.f;

    for (int p = 0; p < 3; p++) {
        const __nv_bfloat16* Ag = Aph[p];
        const __nv_bfloat16* Bg = Bph[p];
        for (int k0 = 0; k0 < N_FEAT; k0 += BKT) {
            __syncthreads();
#pragma unroll
            for (int i = 0; i < 4; i++) {
                int id4 = tid + i * 256;
                int r = id4 >> 3, kk = (id4 & 7) * 8;
                uint4 v = *reinterpret_cast<const uint4*>(
                    Ag + (size_t)(row0 + r) * N_FEAT + k0 + kk);
                *reinterpret_cast<uint4*>(As + r * SA + kk) = v;
            }
#pragma unroll
            for (int i = 0; i < 2; i++) {
                int id4 = tid + i * 256;
                int kk = id4 >> 3, ff = (id4 & 7) * 8;
                uint4 v = *reinterpret_cast<const uint4*>(
                    Bg + (size_t)(k0 + kk) * N_HID + ff);
                *reinterpret_cast<uint4*>(Bs + kk * SB + ff) = v;
            }
            __syncthreads();
#pragma unroll
            for (int ks = 0; ks < 4; ks++) {
                int kb = ks * 16;
                uint32_t afr[2][4];
#pragma unroll
                for (int mm = 0; mm < 2; mm++) {
                    uint32_t addr = sa_base +
                        (uint32_t)((wm * 32 + mm * 16 + idx15) * SA + kb + hi8) * 2u;
                    ldmat_x4(afr[mm], addr);
                }
                uint32_t bfr[4][2];
#pragma unroll
                for (int bp = 0; bp < 2; bp++) {
                    uint32_t bt[4];
                    uint32_t addr = sb_base +
                        (uint32_t)((kb + idx15) * SB + wn * 32 + bp * 16 + hi8) * 2u;
                    ldmat_x4_t(bt, addr);
                    bfr[bp * 2][0] = bt[0]; bfr[bp * 2][1] = bt[1];
                    bfr[bp * 2 + 1][0] = bt[2]; bfr[bp * 2 + 1][1] = bt[3];
                }
#pragma unroll
                for (int mm = 0; mm < 2; mm++)
#pragma unroll
                    for (int nn = 0; nn < 4; nn++)
                        mma16816(acc[mm][nn], afr[mm], bfr[nn]);
            }
        }
    }
#pragma unroll
    for (int mm = 0; mm < 2; mm++)
#pragma unroll
        for (int nn = 0; nn < 4; nn++) {
            int r = row0 + wm * 32 + mm * 16 + lr;
            int c = wn * 32 + nn * 8 + lc * 2;
            float* o = h1 + ((size_t)h * N_ROWS + r) * N_HID + c;
            *reinterpret_cast<float2*>(o) = make_float2(acc[mm][nn][0], acc[mm][nn][1]);
            *reinterpret_cast<float2*>(o + 8 * N_HID) = make_float2(acc[mm][nn][2], acc[mm][nn][3]);
        }

    const float* a = ah + (size_t)h * 2 * N_HID;
#pragma unroll
    for (int mm = 0; mm < 2; mm++) {
        float ps1 = 0.f, pd1 = 0.f, ps2 = 0.f, pd2 = 0.f;
#pragma unroll
        for (int nn = 0; nn < 4; nn++) {
            int c0 = wn * 32 + nn * 8 + lc * 2;
            float a0s = a[c0], a1s = a[c0 + 1];
            float a0d = a[N_HID + c0], a1d = a[N_HID + c0 + 1];
            ps1 += acc[mm][nn][0] * a0s + acc[mm][nn][1] * a1s;
            pd1 += acc[mm][nn][0] * a0d + acc[mm][nn][1] * a1d;
            ps2 += acc[mm][nn][2] * a0s + acc[mm][nn][3] * a1s;
            pd2 += acc[mm][nn][2] * a0d + acc[mm][nn][3] * a1d;
        }
#pragma unroll
        for (int off = 1; off <= 2; off <<= 1) {
            ps1 += __shfl_xor_sync(0xffffffffu, ps1, off);
            pd1 += __shfl_xor_sync(0xffffffffu, pd1, off);
            ps2 += __shfl_xor_sync(0xffffffffu, ps2, off);
            pd2 += __shfl_xor_sync(0xffffffffu, pd2, off);
        }
        if (lc == 0) {
            int rl = wm * 32 + mm * 16 + lr;
            sred[wn][0][rl] = ps1; sred[wn][1][rl] = pd1;
            sred[wn][0][rl + 8] = ps2; sred[wn][1][rl + 8] = pd2;
        }
    }
    __syncthreads();
    if (tid < BM) {
        int gi = h * N_ROWS + row0 + tid;
        ssrc[gi] = sred[0][0][tid] + sred[1][0][tid];
        sdst[gi] = sred[0][1][tid] + sred[1][1][tid];
    }
}

// ---------------- megaAll: both layers' tails in ONE persistent kernel ----------------
__global__ __launch_bounds__(1024, 1) void megaAll_kernel(
    const float* __restrict__ sdst1, float* __restrict__ csort1,
    float* __restrict__ sorted1, int* __restrict__ idx1,
    float* __restrict__ Zhi1, float* __restrict__ Zlo1,
    float* __restrict__ Ze1, float* __restrict__ Zg1,
    const float* __restrict__ h1, float* __restrict__ Chi1, float* __restrict__ Clo1,
    float* __restrict__ Phi1, float* __restrict__ Plo1,
    const float* __restrict__ ssrc1, float* __restrict__ xc,
    const float* __restrict__ Wo, const float* __restrict__ ao,
    float* __restrict__ h2, float* __restrict__ ssrc2, float* __restrict__ sdst2,
    float* __restrict__ csort2, float* __restrict__ sorted2, int* __restrict__ idx2,
    float* __restrict__ Zhi2, float* __restrict__ Zlo2,
    float* __restrict__ Ze2, float* __restrict__ Zg2,
    float* __restrict__ Chi2, float* __restrict__ Clo2,
    float* __restrict__ Phi2, float* __restrict__ Plo2,
    float* __restrict__ out)
{
    __shared__ __align__(16) unsigned char sm[33792];
    int blk = blockIdx.x, t = threadIdx.x;
    int h = blk >> 4, chunk = blk & 15;

    // ======== LAYER 1 tail ========
    // ---- S_a1: chunk sorts (64 blocks) ----
    if (blk < 64) sortchunk_body(blk >> 3, blk & 7, sdst1, csort1, (float*)sm);
    gbar();
    // ---- S_b1: rank + scatter + idx (64 blocks) ----
    if (blk < 64) rank_body(blk >> 3, blk & 7, sdst1, csort1, sorted1, idx1,
                            (float*)sm, (int*)(sm + 16384));
    gbar();

    float M1 = sorted1[(size_t)h * N_ROWS];

    // ---- Phase A1: featA chunk sums + Z chunk sums ----
    {
        int* sidx = (int*)sm;
        float* sew = (float*)(sm + 1024);
        float* sgw = (float*)(sm + 2048);
        float (*sH)[N_HID] = (float(*)[N_HID])(sm + 3072);
        float (*sL)[N_HID] = (float(*)[N_HID])(sm + 7168);
        int ft = t & 63, rg = t >> 6;
        if (t < 256) {
            int base = h * N_ROWS + chunk * 256 + t;
            sidx[t] = idx1[base];
            float v = sorted1[base] - M1;
            sew[t] = expf(v); sgw[t] = expf(0.2f * v);
        }
        __syncthreads();
        const float* hb = h1 + (size_t)h * N_ROWS * N_HID + ft;
        float sh_ = 0.f, sl_ = 0.f;
#pragma unroll
        for (int j = 0; j < 16; j++) {
            int rl = rg * 16 + j;
            float v = hb[(size_t)sidx[rl] * N_HID];
            sh_ += v * sew[rl];
            sl_ += v * sgw[rl];
        }
        sH[rg][ft] = sh_; sL[rg][ft] = sl_;
        __syncthreads();
        if (rg == 0) {
            float a = 0.f, b = 0.f;
#pragma unroll
            for (int r = 0; r < 16; r++) { a += sH[r][ft]; b += sL[r][ft]; }
            Chi1[(h * N_HID + ft) * 16 + chunk] = a;
            Clo1[(h * N_HID + ft) * 16 + chunk] = b;
        }
        if (t < 32) {
            float za = 0.f, zb = 0.f;
#pragma unroll
            for (int i = 0; i < 8; i++) { za += sew[t + i * 32]; zb += sgw[t + i * 32]; }
#pragma unroll
            for (int off = 16; off; off >>= 1) {
                za += __shfl_xor_sync(0xffffffffu, za, off);
                zb += __shfl_xor_sync(0xffffffffu, zb, off);
            }
            if (t == 0) { Ze1[h * 16 + chunk] = za; Zg1[h * 16 + chunk] = zb; }
        }
    }
    gbar();

    // ---- Phase C1: featC final scan + Z prefix ----
    {
        int* sidx = (int*)sm;
        float* sew = (float*)(sm + 1024);
        float* sgw = (float*)(sm + 2048);
        float* sChi = (float*)(sm + 3072);
        float* sClo = (float*)(sm + 7168);
        float (*sH)[N_HID] = (float(*)[N_HID])(sm + 11264);
        float (*sL)[N_HID] = (float(*)[N_HID])(sm + 15360);
        float* sZe = (float*)(sm + 19456);
        float* sZg = (float*)(sm + 19520);
        float* segZ = (float*)(sm + 19584);
        float* segG = (float*)(sm + 19648);
        int ft = t & 63, rg = t >> 6;
        if (t < 256) {
            int base = h * N_ROWS + chunk * 256 + t;
            sidx[t] = idx1[base];
            float v = sorted1[base] - M1;
            sew[t] = expf(v); sgw[t] = expf(0.2f * v);
        }
        if (t < 16) { sZe[t] = Ze1[h * 16 + t]; sZg[t] = Zg1[h * 16 + t]; }
        sChi[t] = Chi1[h * N_HID * 16 + t];
        sClo[t] = Clo1[h * N_HID * 16 + t];
        __syncthreads();
        const float* hb = h1 + (size_t)h * N_ROWS * N_HID + ft;
        float vh[16], vl[16];
        float sh_ = 0.f, sl_ = 0.f;
#pragma unroll
        for (int j = 0; j < 16; j++) {
            int rl = rg * 16 + j;
            float v = hb[(size_t)sidx[rl] * N_HID];
            vh[j] = v * sew[rl];
            vl[j] = v * sgw[rl];
            sh_ += vh[j]; sl_ += vl[j];
        }
        sH[rg][ft] = sh_; sL[rg][ft] = sl_;
        if (ft == 0) {
            float sz = 0.f, sg_ = 0.f;
#pragma unroll
            for (int j = 0; j < 16; j++) { sz += sew[rg * 16 + j]; sg_ += sgw[rg * 16 + j]; }
            segZ[rg] = sz; segG[rg] = sg_;
        }
        __syncthreads();
        float offh = 0.f, offl = 0.f, totl = 0.f;
#pragma unroll
        for (int c = 0; c < 16; c++) {
            float a = sChi[ft * 16 + c], b = sClo[ft * 16 + c];
            if (c < chunk) { offh += a; offl += b; }
            totl += b;
        }
        for (int r = 0; r < rg; r++) { offh += sH[r][ft]; offl += sL[r][ft]; }
        float* PH = Phi1 + (size_t)h * KR * N_HID + ft;
        float* PL = Plo1 + (size_t)h * KR * N_HID + ft;
        float runh = offh, runl = offl;
        int k0 = chunk * 256 + rg * 16;
#pragma unroll
        for (int j = 0; j < 16; j++) {
            PH[(size_t)(k0 + j) * N_HID] = runh;
            PL[(size_t)(k0 + j) * N_HID] = totl - runl;
            runh += vh[j];
            runl += vl[j];
        }
        if (chunk == 15 && rg == 15) {
            PH[(size_t)N_ROWS * N_HID] = runh;
            PL[(size_t)N_ROWS * N_HID] = totl - runl;
        }
        if (ft == 0) {
            float offZ = 0.f, offG = 0.f, totG = 0.f;
#pragma unroll
            for (int c = 0; c < 16; c++) {
                float a = sZe[c], b = sZg[c];
                if (c < chunk) { offZ += a; offG += b; }
                totG += b;
            }
            for (int r = 0; r < rg; r++) { offZ += segZ[r]; offG += segG[r]; }
            float* ZH = Zhi1 + (size_t)h * PS;
            float* ZL = Zlo1 + (size_t)h * PS;
            float runZ = offZ, runG = offG;
#pragma unroll
            for (int j = 0; j < 16; j++) {
                ZH[k0 + j] = runZ;
                ZL[k0 + j] = totG - runG;
                runZ += sew[rg * 16 + j];
                runG += sgw[rg * 16 + j];
            }
            if (chunk == 15 && rg == 15) { ZH[N_ROWS] = runZ; ZL[N_ROWS] = 0.f; }
        }
    }
    gbar();

    // ---- Phase B1: combine1 -> xc ----
    {
        float* ss = (float*)sm;
        const float* sb = sorted1 + (size_t)h * N_ROWS;
        *reinterpret_cast<float4*>(ss + t * 4) = *reinterpret_cast<const float4*>(sb + t * 4);
        __syncthreads();
        int warp = t >> 5, lane = t & 31;
        const float* ZH = Zhi1 + (size_t)h * PS;
        const float* ZL = Zlo1 + (size_t)h * PS;
        const float* PHb = Phi1 + (size_t)h * KR * N_HID;
        const float* PLb = Plo1 + (size_t)h * KR * N_HID;
        int i0 = chunk * 256;
#pragma unroll
        for (int rr = 0; rr < 8; rr++) {
            int i = i0 + warp * 8 + rr;
            float s = ssrc1[(size_t)h * N_ROWS + i];
            float thr = -s;
            int lo = 0, hi = N_ROWS;
            while (lo < hi) {
                int mid = (lo + hi) >> 1;
                if (ss[mid] >= thr) lo = mid + 1; else hi = mid;
            }
            int k = lo;
            float rho = expf(-0.8f * (s + M1));
            float den = (k == 0) ? ZL[0] : (ZH[k] + rho * ZL[k]);
            float inv = 1.f / den;
            const float* ph = PHb + (size_t)k * N_HID;
            const float* pl = PLb + (size_t)k * N_HID;
#pragma unroll
            for (int u = 0; u < 2; u++) {
                int f = lane + 32 * u;
                float num = (k == 0) ? pl[f] : (ph[f] + rho * pl[f]);
                float feat = num * inv;
                float v = feat > 0.f ? feat : expm1f(feat);
                xc[(size_t)i * N_FEAT + h * N_HID + f] = v;
            }
        }
    }
    gbar();

    // ======== LAYER 2 tail ========
    // ---- Phase G: gemm2 + fused scores2 ----
    {
        float (*xs)[64] = (float(*)[64])sm;
        float (*ws)[16] = (float(*)[16])(sm + 8192);
        int row0 = blk * 32;
        int ir = t >> 4, fc = t & 15;
        float acc = 0.f;
        for (int k0 = 0; k0 < N_FEAT; k0 += 64) {
            __syncthreads();
#pragma unroll
            for (int rep = 0; rep < 2; rep++) {
                int t2 = t + rep * 1024;
                int r = t2 >> 6, kk = t2 & 63;
                xs[r][kk] = xc[(size_t)(row0 + r) * N_FEAT + k0 + kk];
            }
            {
                int kk = t >> 4, f = t & 15;
                if (kk < 64) ws[kk][f] = Wo[(size_t)(k0 + kk) * N_CLASS + f];
            }
            __syncthreads();
            if (t < 512) {
#pragma unroll
                for (int kk = 0; kk < 64; kk++) acc += xs[ir][kk] * ws[kk][fc];
            }
        }
        if (t < 512) {
            h2[(size_t)(row0 + ir) * N_CLASS + fc] = acc;
            float ps = acc * ao[fc];
            float pd = acc * ao[N_CLASS + fc];
#pragma unroll
            for (int off = 1; off < 16; off <<= 1) {
                ps += __shfl_xor_sync(0xffffffffu, ps, off);
                pd += __shfl_xor_sync(0xffffffffu, pd, off);
            }
            if (fc == 0) {
                ssrc2[row0 + ir] = ps;
                sdst2[row0 + ir] = pd;
            }
        }
    }
    gbar();

    if (blk < 8) sortchunk_body(0, blk, sdst2, csort2, (float*)sm);
    gbar();
    if (blk < 8) rank_body(0, blk, sdst2, csort2, sorted2, idx2,
                           (float*)sm, (int*)(sm + 16384));
    gbar();

    float M2 = sorted2[0];

    // ---- Phase A2: chunk sums + Z chunk sums (blocks 0..15) ----
    if (blk < 16) {
        int chunk2 = blk;
        int* sidx = (int*)sm;
        float* sew = (float*)(sm + 1024);
        float* sgw = (float*)(sm + 2048);
        float (*sH)[N_CLASS] = (float(*)[N_CLASS])(sm + 3072);
        float (*sL)[N_CLASS] = (float(*)[N_CLASS])(sm + 7168);
        if (t < 256) {
            int base = chunk2 * 256 + t;
            sidx[t] = idx2[base];
            float v = sorted2[base] - M2;
            sew[t] = expf(v); sgw[t] = expf(0.2f * v);
        }
        __syncthreads();
        int ft = t & 15, rg = t >> 4;
        const float* hb = h2 + ft;
        float a = 0.f, b = 0.f;
#pragma unroll
        for (int j = 0; j < 4; j++) {
            int rl = rg * 4 + j;
            float v = hb[(size_t)sidx[rl] * N_CLASS];
            a += v * sew[rl];
            b += v * sgw[rl];
        }
        sH[rg][ft] = a; sL[rg][ft] = b;
        __syncthreads();
        if (t < 16) {
            float sa = 0.f, sb = 0.f;
#pragma unroll
            for (int r = 0; r < 64; r++) { sa += sH[r][t]; sb += sL[r][t]; }
            Chi2[t * 16 + chunk2] = sa;
            Clo2[t * 16 + chunk2] = sb;
        }
        if (t < 32) {
            float za = 0.f, zb = 0.f;
#pragma unroll
            for (int i = 0; i < 8; i++) { za += sew[t + i * 32]; zb += sgw[t + i * 32]; }
#pragma unroll
            for (int off = 16; off; off >>= 1) {
                za += __shfl_xor_sync(0xffffffffu, za, off);
                zb += __shfl_xor_sync(0xffffffffu, zb, off);
            }
            if (t == 0) { Ze2[chunk2] = za; Zg2[chunk2] = zb; }
        }
    }
    gbar();

    // ---- Phase C2: final scan + Z prefix (blocks 0..15) ----
    if (blk < 16) {
        int chunk2 = blk;
        int* sidx = (int*)sm;
        float* sew = (float*)(sm + 1024);
        float* sgw = (float*)(sm + 2048);
        float (*sH)[N_CLASS] = (float(*)[N_CLASS])(sm + 3072);
        float (*sL)[N_CLASS] = (float(*)[N_CLASS])(sm + 7168);
        float* sChi = (float*)(sm + 11264);
        float* sClo = (float*)(sm + 12288);
        float* sZe = (float*)(sm + 13312);
        float* sZg = (float*)(sm + 13376);
        float* segZ = (float*)(sm + 13440);
        float* segG = (float*)(sm + 13696);
        if (t < 256) {
            int base = chunk2 * 256 + t;
            sidx[t] = idx2[base];
            float v = sorted2[base] - M2;
            sew[t] = expf(v); sgw[t] = expf(0.2f * v);
            sChi[t] = Chi2[t]; sClo[t] = Clo2[t];
        }
        if (t < 16) { sZe[t] = Ze2[t]; sZg[t] = Zg2[t]; }
        __syncthreads();
        int ft = t & 15, rg = t >> 4;
        const float* hb = h2 + ft;
        float vh[4], vl[4];
        float a = 0.f, b = 0.f;
#pragma unroll
        for (int j = 0; j < 4; j++) {
            int rl = rg * 4 + j;
            float v = hb[(size_t)sidx[rl] * N_CLASS];
            vh[j] = v * sew[rl];
            vl[j] = v * sgw[rl];
            a += vh[j]; b += vl[j];
        }
        sH[rg][ft] = a; sL[rg][ft] = b;
        if (ft == 0) {
            float sz = 0.f, sg_ = 0.f;
#pragma unroll
            for (int j = 0; j < 4; j++) { sz += sew[rg * 4 + j]; sg_ += sgw[rg * 4 + j]; }
            segZ[rg] = sz; segG[rg] = sg_;
        }
        __syncthreads();
        float offh = 0.f, offl = 0.f, totl = 0.f;
#pragma unroll
        for (int c = 0; c < 16; c++) {
            float ca = sChi[ft * 16 + c], cb = sClo[ft * 16 + c];
            if (c < chunk2) { offh += ca; offl += cb; }
            totl += cb;
        }
        for (int r = 0; r < rg; r++) { offh += sH[r][ft]; offl += sL[r][ft]; }
        float runh = offh, runl = offl;
        int k0 = chunk2 * 256 + rg * 4;
#pragma unroll
        for (int j = 0; j < 4; j++) {
            Phi2[(size_t)(k0 + j) * N_CLASS + ft] = runh;
            Plo2[(size_t)(k0 + j) * N_CLASS + ft] = totl - runl;
            runh += vh[j];
            runl += vl[j];
        }
        if (chunk2 == 15 && rg == 63) {
            Phi2[(size_t)N_ROWS * N_CLASS + ft] = runh;
            Plo2[(size_t)N_ROWS * N_CLASS + ft] = totl - runl;
        }
        if (ft == 0) {
            float offZ = 0.f, offG = 0.f, totG = 0.f;
#pragma unroll
            for (int c = 0; c < 16; c++) {
                float ca = sZe[c], cb = sZg[c];
                if (c < chunk2) { offZ += ca; offG += cb; }
                totG += cb;
            }
            for (int r = 0; r < rg; r++) { offZ += segZ[r]; offG += segG[r]; }
            float runZ = offZ, runG = offG;
#pragma unroll
            for (int j = 0; j < 4; j++) {
                Zhi2[k0 + j] = runZ;
                Zlo2[k0 + j] = totG - runG;
                runZ += sew[rg * 4 + j];
                runG += sgw[rg * 4 + j];
            }
            if (chunk2 == 15 && rg == 63) { Zhi2[N_ROWS] = runZ; Zlo2[N_ROWS] = 0.f; }
        }
    }
    gbar();

    // ---- Phase B2 ----
    if (blk < 64) {
        float* ss = (float*)sm;
        *reinterpret_cast<float4*>(ss + t * 4) = *reinterpret_cast<const float4*>(sorted2 + t * 4);
        __syncthreads();
        int f = t & 15, il = t >> 4;
        int i = blk * 64 + il;
        float s = ssrc2[i];
        float thr = -s;
        int lo = 0, hi = N_ROWS;
        while (lo < hi) {
            int mid = (lo + hi) >> 1;
            if (ss[mid] >= thr) lo = mid + 1; else hi = mid;
        }
        int k = lo;
        float rho = expf(-0.8f * (s + M2));
        float den = (k == 0) ? Zlo2[0] : (Zhi2[k] + rho * Zlo2[k]);
        float num = (k == 0) ? Plo2[f]
                             : (Phi2[(size_t)k * N_CLASS + f] + rho * Plo2[(size_t)k * N_CLASS + f]);
        float feat = num / den;
        float v = feat > 0.f ? feat : expm1f(feat);
        float m = v;
#pragma unroll
        for (int off = 8; off; off >>= 1) m = fmaxf(m, __shfl_xor_sync(0xffffffffu, m, off));
        float ex = expf(v - m);
        float ssum = ex;
#pragma unroll
        for (int off = 8; off; off >>= 1) ssum += __shfl_xor_sync(0xffffffffu, ssum, off);
        out[(size_t)i * N_CLASS + f] = v - m - logf(ssum);
    }
}

// ---------------- launch ----------------
extern "C" void kernel_launch(void* const* d_in, const int* in_sizes, int n_in,
                              void* d_out, int out_size)
{
    const float* x  = (const float*)d_in[0];
    const float* Wh = (const float*)d_in[1];
    const float* ah = (const float*)d_in[2];
    const float* Wo = (const float*)d_in[3];
    const float* ao = (const float*)d_in[4];
    float* out = (float*)d_out;

    __nv_bfloat16 *p_xh, *p_xl, *p_whh, *p_whl;
    float *p_h1, *p_ssrc1, *p_sdst1, *p_csort1, *p_sorted1, *p_Zhi1, *p_Zlo1, *p_Ze1, *p_Zg1;
    float *p_Chi1, *p_Clo1, *p_Phi1, *p_Plo1, *p_xc;
    int *p_idx1;
    float *p_h2, *p_ssrc2, *p_sdst2, *p_csort2, *p_sorted2, *p_Zhi2, *p_Zlo2, *p_Ze2, *p_Zg2;
    float *p_Chi2, *p_Clo2, *p_Phi2, *p_Plo2;
    int *p_idx2;

    cudaGetSymbolAddress((void**)&p_xh, g_xh);
    cudaGetSymbolAddress((void**)&p_xl, g_xl);
    cudaGetSymbolAddress((void**)&p_whh, g_whh);
    cudaGetSymbolAddress((void**)&p_whl, g_whl);
    cudaGetSymbolAddress((void**)&p_h1, g_h1);
    cudaGetSymbolAddress((void**)&p_ssrc1, g_ssrc1);
    cudaGetSymbolAddress((void**)&p_sdst1, g_sdst1);
    cudaGetSymbolAddress((void**)&p_csort1, g_csort1);
    cudaGetSymbolAddress((void**)&p_sorted1, g_sorted1);
    cudaGetSymbolAddress((void**)&p_idx1, g_idx1);
    cudaGetSymbolAddress((void**)&p_Zhi1, g_Zhi1);
    cudaGetSymbolAddress((void**)&p_Zlo1, g_Zlo1);
    cudaGetSymbolAddress((void**)&p_Ze1, g_Ze1);
    cudaGetSymbolAddress((void**)&p_Zg1, g_Zg1);
    cudaGetSymbolAddress((void**)&p_Chi1, g_Chi1);
    cudaGetSymbolAddress((void**)&p_Clo1, g_Clo1);
    cudaGetSymbolAddress((void**)&p_Phi1, g_Phi1);
    cudaGetSymbolAddress((void**)&p_Plo1, g_Plo1);
    cudaGetSymbolAddress((void**)&p_xc, g_xc);
    cudaGetSymbolAddress((void**)&p_h2, g_h2);
    cudaGetSymbolAddress((void**)&p_ssrc2, g_ssrc2);
    cudaGetSymbolAddress((void**)&p_sdst2, g_sdst2);
    cudaGetSymbolAddress((void**)&p_csort2, g_csort2);
    cudaGetSymbolAddress((void**)&p_sorted2, g_sorted2);
    cudaGetSymbolAddress((void**)&p_idx2, g_idx2);
    cudaGetSymbolAddress((void**)&p_Zhi2, g_Zhi2);
    cudaGetSymbolAddress((void**)&p_Zlo2, g_Zlo2);
    cudaGetSymbolAddress((void**)&p_Ze2, g_Ze2);
    cudaGetSymbolAddress((void**)&p_Zg2, g_Zg2);
    cudaGetSymbolAddress((void**)&p_Chi2, g_Chi2);
    cudaGetSymbolAddress((void**)&p_Clo2, g_Clo2);
    cudaGetSymbolAddress((void**)&p_Phi2, g_Phi2);
    cudaGetSymbolAddress((void**)&p_Plo2, g_Plo2);

    splitall_kernel<<<(NX4 + NW4 + 255) / 256, 256>>>(x, Wh, p_xh, p_xl, p_whh, p_whl);
    gemm1_mma_kernel<<<dim3(N_ROWS / 128, N_HEADS), 256>>>(p_xh, p_xl, p_whh, p_whl, ah,
                                                           p_h1, p_ssrc1, p_sdst1);
    megaAll_kernel<<<NB, 1024>>>(p_sdst1, p_csort1, p_sorted1, p_idx1,
                                 p_Zhi1, p_Zlo1, p_Ze1, p_Zg1,
                                 p_h1, p_Chi1, p_Clo1, p_Phi1, p_Plo1, p_ssrc1, p_xc,
                                 Wo, ao, p_h2, p_ssrc2, p_sdst2,
                                 p_csort2, p_sorted2, p_idx2,
                                 p_Zhi2, p_Zlo2, p_Ze2, p_Zg2,
                                 p_Chi2, p_Clo2, p_Phi2, p_Plo2, out);

    (void)in_sizes; (void)n_in; (void)out_size;
}

// round 17
// speedup vs baseline: 1.0646x; 1.0646x over previous
#include <cuda_runtime.h>
#include <cuda_bf16.h>
#include <cstdint>

#define N_ROWS   4096
#define N_FEAT   512
#define N_HID    64
#define N_CLASS  16
#define N_HEADS  8
#define PS       (N_ROWS + 4)
#define KR       (N_ROWS + 1)
#define NB       128            // mega-kernel grid size (all-resident)

// ---------------- scratch ----------------
__device__ float g_h1   [N_HEADS*N_ROWS*N_HID];
__device__ float g_ssrc1[N_HEADS*N_ROWS];
__device__ float g_sdst1[N_HEADS*N_ROWS];
__device__ float g_csort1[N_HEADS*N_ROWS];
__device__ float g_sorted1[N_HEADS*N_ROWS];
__device__ int   g_idx1 [N_HEADS*N_ROWS];
__device__ float g_Zhi1 [N_HEADS*PS];
__device__ float g_Zlo1 [N_HEADS*PS];
__device__ float g_Ze1  [N_HEADS*16];
__device__ float g_Zg1  [N_HEADS*16];
__device__ float g_Chi1 [N_HEADS*N_HID*16];
__device__ float g_Clo1 [N_HEADS*N_HID*16];
__device__ float g_Phi1 [N_HEADS*KR*N_HID];
__device__ float g_Plo1 [N_HEADS*KR*N_HID];
__device__ float g_xc   [N_ROWS*N_FEAT];

__device__ float g_h2   [N_ROWS*N_CLASS];
__device__ float g_ssrc2[N_ROWS];
__device__ float g_sdst2[N_ROWS];
__device__ float g_csort2[N_ROWS];
__device__ float g_sorted2[N_ROWS];
__device__ int   g_idx2 [N_ROWS];
__device__ float g_Zhi2 [PS];
__device__ float g_Zlo2 [PS];
__device__ float g_Ze2  [16];
__device__ float g_Zg2  [16];
__device__ float g_Chi2 [N_CLASS*16];
__device__ float g_Clo2 [N_CLASS*16];
__device__ float g_Phi2 [KR*N_CLASS];
__device__ float g_Plo2 [KR*N_CLASS];

// ---------------- device-wide software barrier ----------------
__device__ unsigned g_cnt;
__device__ volatile unsigned g_gen;

__device__ __forceinline__ void gbar() {
    __syncthreads();
    if (threadIdx.x == 0) {
        __threadfence();
        unsigned old = g_gen;
        if (atomicAdd(&g_cnt, 1u) == NB - 1) {
            g_cnt = 0;
            __threadfence();
            g_gen = old + 1;
        } else {
            while (g_gen == old) { __nanosleep(64); }
            __threadfence();
        }
    }
    __syncthreads();
}

// ---------------- S_a: sort one 512-chunk (descending), 1 elem/thread ----------------
__device__ void sortchunk_body(int h, int c, const float* __restrict__ sdst,
                               float* __restrict__ csort, float* sk)
{
    int tid = threadIdx.x;
    float key = 0.f;
    if (tid < 512) key = sdst[(size_t)h * N_ROWS + c * 512 + tid];
    for (int k = 2; k <= 512; k <<= 1) {
        for (int j = k >> 1; j > 0; j >>= 1) {
            if (j >= 32) {
                __syncthreads();
                if (tid < 512) sk[tid] = key;
                __syncthreads();
                if (tid < 512) {
                    float ok = sk[tid ^ j];
                    bool lower = (tid & j) == 0;
                    bool desc = ((tid & k & 511) == 0);
                    float a = lower ? key : ok, b = lower ? ok : key;
                    if (desc ? (a < b) : (a > b)) key = ok;
                }
            } else {
                if (tid < 512) {
                    float ok = __shfl_xor_sync(0xffffffffu, key, j);
                    bool lower = (tid & j) == 0;
                    bool desc = ((tid & k & 511) == 0);
                    float a = lower ? key : ok, b = lower ? ok : key;
                    if (desc ? (a < b) : (a > b)) key = ok;
                }
            }
        }
    }
    __syncthreads();
    if (tid < 512) csort[(size_t)h * N_ROWS + c * 512 + tid] = key;
}

// ---------------- S_b: rank own chunk + scatter sorted + idx recovery ----------------
__device__ void rank_body(int h, int c, const float* __restrict__ sdst,
                          const float* __restrict__ csort,
                          float* __restrict__ sorted, int* __restrict__ idx,
                          float* skeys, int* grank)
{
    int tid = threadIdx.x;
#pragma unroll
    for (int i = 0; i < 4; i++) skeys[tid + i * 1024] = csort[(size_t)h * N_ROWS + tid + i * 1024];
    __syncthreads();
    if (tid < 512) {
        float x = skeys[c * 512 + tid];
        int r = tid;
#pragma unroll
        for (int cc = 0; cc < 8; cc++) {
            if (cc == c) continue;
            const float* S = skeys + cc * 512;
            int lo = 0, hi = 512;
            if (cc < c) {
                while (lo < hi) { int mid = (lo + hi) >> 1; if (S[mid] >= x) lo = mid + 1; else hi = mid; }
            } else {
                while (lo < hi) { int mid = (lo + hi) >> 1; if (S[mid] > x) lo = mid + 1; else hi = mid; }
            }
            r += lo;
        }
        grank[tid] = r;
        sorted[(size_t)h * N_ROWS + r] = x;
    }
    __syncthreads();
    if (tid < 512) {
        int j = c * 512 + tid;
        float x = sdst[(size_t)h * N_ROWS + j];
        const float* S = skeys + c * 512;
        int lo = 0, hi = 512;
        while (lo < hi) { int mid = (lo + hi) >> 1; if (S[mid] > x) lo = mid + 1; else hi = mid; }
        int off = atomicAdd(&grank[lo], 0x10000) >> 16;
        int rank = grank[lo + off] & 0xFFFF;
        idx[(size_t)h * N_ROWS + rank] = j;
    }
    __syncthreads();
}

// ---------------- GEMM1: fused fp32->bf16 hi/lo split + single-pass 3-term mma ----------------
__device__ __forceinline__ void mma16816(float* c, const uint32_t* a, const uint32_t* b) {
    asm volatile(
        "mma.sync.aligned.m16n8k16.row.col.f32.bf16.bf16.f32 "
        "{%0,%1,%2,%3}, {%4,%5,%6,%7}, {%8,%9}, {%0,%1,%2,%3};\n"
        : "+f"(c[0]), "+f"(c[1]), "+f"(c[2]), "+f"(c[3])
        : "r"(a[0]), "r"(a[1]), "r"(a[2]), "r"(a[3]), "r"(b[0]), "r"(b[1]));
}
__device__ __forceinline__ void ldmat_x4(uint32_t* r, uint32_t addr) {
    asm volatile("ldmatrix.sync.aligned.m8n8.x4.shared.b16 {%0,%1,%2,%3}, [%4];"
        : "=r"(r[0]), "=r"(r[1]), "=r"(r[2]), "=r"(r[3]) : "r"(addr));
}
__device__ __forceinline__ void ldmat_x4_t(uint32_t* r, uint32_t addr) {
    asm volatile("ldmatrix.sync.aligned.m8n8.x4.trans.shared.b16 {%0,%1,%2,%3}, [%4];"
        : "=r"(r[0]), "=r"(r[1]), "=r"(r[2]), "=r"(r[3]) : "r"(addr));
}

__device__ __forceinline__ void split4(float4 v, __nv_bfloat16* hp, __nv_bfloat16* lp) {
    __nv_bfloat16 b0 = __float2bfloat16_rn(v.x);
    __nv_bfloat16 b1 = __float2bfloat16_rn(v.y);
    __nv_bfloat16 b2 = __float2bfloat16_rn(v.z);
    __nv_bfloat16 b3 = __float2bfloat16_rn(v.w);
    __nv_bfloat16 c0 = __float2bfloat16_rn(v.x - __bfloat162float(b0));
    __nv_bfloat16 c1 = __float2bfloat16_rn(v.y - __bfloat162float(b1));
    __nv_bfloat16 c2 = __float2bfloat16_rn(v.z - __bfloat162float(b2));
    __nv_bfloat16 c3 = __float2bfloat16_rn(v.w - __bfloat162float(b3));
    reinterpret_cast<__nv_bfloat162*>(hp)[0] = __nv_bfloat162(b0, b1);
    reinterpret_cast<__nv_bfloat162*>(hp)[1] = __nv_bfloat162(b2, b3);
    reinterpret_cast<__nv_bfloat162*>(lp)[0] = __nv_bfloat162(c0, c1);
    reinterpret_cast<__nv_bfloat162*>(lp)[1] = __nv_bfloat162(c2, c3);
}

__global__ __launch_bounds__(256) void gemm1_mma_kernel(
    const float* __restrict__ x, const float* __restrict__ Wh,
    const float* __restrict__ ah,
    float* __restrict__ h1, float* __restrict__ ssrc, float* __restrict__ sdst)
{
    const int BM = 128, BKT = 32, SA = 40, SB = 72;
    __shared__ __nv_bfloat16 Ah[BM * SA], Al[BM * SA];    // 10240 B each
    __shared__ __nv_bfloat16 Bh[BKT * SB], Bl[BKT * SB];  // 4608 B each
    __shared__ float sred[2][2][BM];
    int h = blockIdx.y;
    int row0 = blockIdx.x * BM;
    int tid = threadIdx.x;
    int wid = tid >> 5, lane = tid & 31;
    int wm = wid & 3, wn = wid >> 2;
    int lr = lane >> 2, lc = lane & 3;
    int idx15 = lane & 15, hi8 = (lane >> 4) << 3;

    uint32_t ahb = (uint32_t)__cvta_generic_to_shared(Ah);
    uint32_t alb = (uint32_t)__cvta_generic_to_shared(Al);
    uint32_t bhb = (uint32_t)__cvta_generic_to_shared(Bh);
    uint32_t blb = (uint32_t)__cvta_generic_to_shared(Bl);

    const float* Wb = Wh + (size_t)h * N_FEAT * N_HID;

    float acc[2][4][4];
#pragma unroll
    for (int mm = 0; mm < 2; mm++)
#pragma unroll
        for (int nn = 0; nn < 4; nn++)
#pragma unroll
            for (int q = 0; q < 4; q++) acc[mm][nn][q] = 0.f;

    for (int k0 = 0; k0 < N_FEAT; k0 += BKT) {
        __syncthreads();
        // x tile: 128 x 32 fp32 -> Ah/Al
#pragma unroll
        for (int i = 0; i < 4; i++) {
            int id4 = tid + i * 256;
            int r = id4 >> 3, kk = (id4 & 7) * 4;
            float4 v = *reinterpret_cast<const float4*>(
                x + (size_t)(row0 + r) * N_FEAT + k0 + kk);
            split4(v, Ah + r * SA + kk, Al + r * SA + kk);
        }
        // W tile: 32 x 64 fp32 -> Bh/Bl
#pragma unroll
        for (int i = 0; i < 2; i++) {
            int id4 = tid + i * 256;
            int kk = id4 >> 4, ff = (id4 & 15) * 4;
            float4 v = *reinterpret_cast<const float4*>(
                Wb + (size_t)(k0 + kk) * N_HID + ff);
            split4(v, Bh + kk * SB + ff, Bl + kk * SB + ff);
        }
        __syncthreads();
#pragma unroll
        for (int ks = 0; ks < 2; ks++) {
            int kb = ks * 16;
            uint32_t afh[2][4], afl[2][4];
#pragma unroll
            for (int mm = 0; mm < 2; mm++) {
                uint32_t off = (uint32_t)((wm * 32 + mm * 16 + idx15) * SA + kb + hi8) * 2u;
                ldmat_x4(afh[mm], ahb + off);
                ldmat_x4(afl[mm], alb + off);
            }
            uint32_t bfh[4][2], bfl[4][2];
#pragma unroll
            for (int bp = 0; bp < 2; bp++) {
                uint32_t off = (uint32_t)((kb + idx15) * SB + wn * 32 + bp * 16 + hi8) * 2u;
                uint32_t bt[4];
                ldmat_x4_t(bt, bhb + off);
                bfh[bp * 2][0] = bt[0]; bfh[bp * 2][1] = bt[1];
                bfh[bp * 2 + 1][0] = bt[2]; bfh[bp * 2 + 1][1] = bt[3];
                ldmat_x4_t(bt, blb + off);
                bfl[bp * 2][0] = bt[0]; bfl[bp * 2][1] = bt[1];
                bfl[bp * 2 + 1][0] = bt[2]; bfl[bp * 2 + 1][1] = bt[3];
            }
#pragma unroll
            for (int mm = 0; mm < 2; mm++)
#pragma unroll
                for (int nn = 0; nn < 4; nn++) {
                    mma16816(acc[mm][nn], afh[mm], bfh[nn]);
                    mma16816(acc[mm][nn], afl[mm], bfh[nn]);
                    mma16816(acc[mm][nn], afh[mm], bfl[nn]);
                }
        }
    }
    // store h1 tile
#pragma unroll
    for (int mm = 0; mm < 2; mm++)
#pragma unroll
        for (int nn = 0; nn < 4; nn++) {
            int r = row0 + wm * 32 + mm * 16 + lr;
            int c = wn * 32 + nn * 8 + lc * 2;
            float* o = h1 + ((size_t)h * N_ROWS + r) * N_HID + c;
            *reinterpret_cast<float2*>(o) = make_float2(acc[mm][nn][0], acc[mm][nn][1]);
            *reinterpret_cast<float2*>(o + 8 * N_HID) = make_float2(acc[mm][nn][2], acc[mm][nn][3]);
        }

    // fused scores epilogue
    const float* a = ah + (size_t)h * 2 * N_HID;
#pragma unroll
    for (int mm = 0; mm < 2; mm++) {
        float ps1 = 0.f, pd1 = 0.f, ps2 = 0.f, pd2 = 0.f;
#pragma unroll
        for (int nn = 0; nn < 4; nn++) {
            int c0 = wn * 32 + nn * 8 + lc * 2;
            float a0s = a[c0], a1s = a[c0 + 1];
            float a0d = a[N_HID + c0], a1d = a[N_HID + c0 + 1];
            ps1 += acc[mm][nn][0] * a0s + acc[mm][nn][1] * a1s;
            pd1 += acc[mm][nn][0] * a0d + acc[mm][nn][1] * a1d;
            ps2 += acc[mm][nn][2] * a0s + acc[mm][nn][3] * a1s;
            pd2 += acc[mm][nn][2] * a0d + acc[mm][nn][3] * a1d;
        }
#pragma unroll
        for (int off = 1; off <= 2; off <<= 1) {
            ps1 += __shfl_xor_sync(0xffffffffu, ps1, off);
            pd1 += __shfl_xor_sync(0xffffffffu, pd1, off);
            ps2 += __shfl_xor_sync(0xffffffffu, ps2, off);
            pd2 += __shfl_xor_sync(0xffffffffu, pd2, off);
        }
        if (lc == 0) {
            int rl = wm * 32 + mm * 16 + lr;
            sred[wn][0][rl] = ps1; sred[wn][1][rl] = pd1;
            sred[wn][0][rl + 8] = ps2; sred[wn][1][rl + 8] = pd2;
        }
    }
    __syncthreads();
    if (tid < BM) {
        int gi = h * N_ROWS + row0 + tid;
        ssrc[gi] = sred[0][0][tid] + sred[1][0][tid];
        sdst[gi] = sred[0][1][tid] + sred[1][1][tid];
    }
}

// ---------------- megaAll: both layers' tails in ONE persistent kernel ----------------
__global__ __launch_bounds__(1024, 1) void megaAll_kernel(
    const float* __restrict__ sdst1, float* __restrict__ csort1,
    float* __restrict__ sorted1, int* __restrict__ idx1,
    float* __restrict__ Zhi1, float* __restrict__ Zlo1,
    float* __restrict__ Ze1, float* __restrict__ Zg1,
    const float* __restrict__ h1, float* __restrict__ Chi1, float* __restrict__ Clo1,
    float* __restrict__ Phi1, float* __restrict__ Plo1,
    const float* __restrict__ ssrc1, float* __restrict__ xc,
    const float* __restrict__ Wo, const float* __restrict__ ao,
    float* __restrict__ h2, float* __restrict__ ssrc2, float* __restrict__ sdst2,
    float* __restrict__ csort2, float* __restrict__ sorted2, int* __restrict__ idx2,
    float* __restrict__ Zhi2, float* __restrict__ Zlo2,
    float* __restrict__ Ze2, float* __restrict__ Zg2,
    float* __restrict__ Chi2, float* __restrict__ Clo2,
    float* __restrict__ Phi2, float* __restrict__ Plo2,
    float* __restrict__ out)
{
    __shared__ __align__(16) unsigned char sm[33792];
    int blk = blockIdx.x, t = threadIdx.x;
    int h = blk >> 4, chunk = blk & 15;

    // ======== LAYER 1 tail ========
    if (blk < 64) sortchunk_body(blk >> 3, blk & 7, sdst1, csort1, (float*)sm);
    gbar();
    if (blk < 64) rank_body(blk >> 3, blk & 7, sdst1, csort1, sorted1, idx1,
                            (float*)sm, (int*)(sm + 16384));
    gbar();

    float M1 = sorted1[(size_t)h * N_ROWS];

    // ---- Phase A1 ----
    {
        int* sidx = (int*)sm;
        float* sew = (float*)(sm + 1024);
        float* sgw = (float*)(sm + 2048);
        float (*sH)[N_HID] = (float(*)[N_HID])(sm + 3072);
        float (*sL)[N_HID] = (float(*)[N_HID])(sm + 7168);
        int ft = t & 63, rg = t >> 6;
        if (t < 256) {
            int base = h * N_ROWS + chunk * 256 + t;
            sidx[t] = idx1[base];
            float v = sorted1[base] - M1;
            sew[t] = expf(v); sgw[t] = expf(0.2f * v);
        }
        __syncthreads();
        const float* hb = h1 + (size_t)h * N_ROWS * N_HID + ft;
        float sh_ = 0.f, sl_ = 0.f;
#pragma unroll
        for (int j = 0; j < 16; j++) {
            int rl = rg * 16 + j;
            float v = hb[(size_t)sidx[rl] * N_HID];
            sh_ += v * sew[rl];
            sl_ += v * sgw[rl];
        }
        sH[rg][ft] = sh_; sL[rg][ft] = sl_;
        __syncthreads();
        if (rg == 0) {
            float a = 0.f, b = 0.f;
#pragma unroll
            for (int r = 0; r < 16; r++) { a += sH[r][ft]; b += sL[r][ft]; }
            Chi1[(h * N_HID + ft) * 16 + chunk] = a;
            Clo1[(h * N_HID + ft) * 16 + chunk] = b;
        }
        if (t < 32) {
            float za = 0.f, zb = 0.f;
#pragma unroll
            for (int i = 0; i < 8; i++) { za += sew[t + i * 32]; zb += sgw[t + i * 32]; }
#pragma unroll
            for (int off = 16; off; off >>= 1) {
                za += __shfl_xor_sync(0xffffffffu, za, off);
                zb += __shfl_xor_sync(0xffffffffu, zb, off);
            }
            if (t == 0) { Ze1[h * 16 + chunk] = za; Zg1[h * 16 + chunk] = zb; }
        }
    }
    gbar();

    // ---- Phase C1 ----
    {
        int* sidx = (int*)sm;
        float* sew = (float*)(sm + 1024);
        float* sgw = (float*)(sm + 2048);
        float* sChi = (float*)(sm + 3072);
        float* sClo = (float*)(sm + 7168);
        float (*sH)[N_HID] = (float(*)[N_HID])(sm + 11264);
        float (*sL)[N_HID] = (float(*)[N_HID])(sm + 15360);
        float* sZe = (float*)(sm + 19456);
        float* sZg = (float*)(sm + 19520);
        float* segZ = (float*)(sm + 19584);
        float* segG = (float*)(sm + 19648);
        int ft = t & 63, rg = t >> 6;
        if (t < 256) {
            int base = h * N_ROWS + chunk * 256 + t;
            sidx[t] = idx1[base];
            float v = sorted1[base] - M1;
            sew[t] = expf(v); sgw[t] = expf(0.2f * v);
        }
        if (t < 16) { sZe[t] = Ze1[h * 16 + t]; sZg[t] = Zg1[h * 16 + t]; }
        sChi[t] = Chi1[h * N_HID * 16 + t];
        sClo[t] = Clo1[h * N_HID * 16 + t];
        __syncthreads();
        const float* hb = h1 + (size_t)h * N_ROWS * N_HID + ft;
        float vh[16], vl[16];
        float sh_ = 0.f, sl_ = 0.f;
#pragma unroll
        for (int j = 0; j < 16; j++) {
            int rl = rg * 16 + j;
            float v = hb[(size_t)sidx[rl] * N_HID];
            vh[j] = v * sew[rl];
            vl[j] = v * sgw[rl];
            sh_ += vh[j]; sl_ += vl[j];
        }
        sH[rg][ft] = sh_; sL[rg][ft] = sl_;
        if (ft == 0) {
            float sz = 0.f, sg_ = 0.f;
#pragma unroll
            for (int j = 0; j < 16; j++) { sz += sew[rg * 16 + j]; sg_ += sgw[rg * 16 + j]; }
            segZ[rg] = sz; segG[rg] = sg_;
        }
        __syncthreads();
        float offh = 0.f, offl = 0.f, totl = 0.f;
#pragma unroll
        for (int c = 0; c < 16; c++) {
            float a = sChi[ft * 16 + c], b = sClo[ft * 16 + c];
            if (c < chunk) { offh += a; offl += b; }
            totl += b;
        }
        for (int r = 0; r < rg; r++) { offh += sH[r][ft]; offl += sL[r][ft]; }
        float* PH = Phi1 + (size_t)h * KR * N_HID + ft;
        float* PL = Plo1 + (size_t)h * KR * N_HID + ft;
        float runh = offh, runl = offl;
        int k0 = chunk * 256 + rg * 16;
#pragma unroll
        for (int j = 0; j < 16; j++) {
            PH[(size_t)(k0 + j) * N_HID] = runh;
            PL[(size_t)(k0 + j) * N_HID] = totl - runl;
            runh += vh[j];
            runl += vl[j];
        }
        if (chunk == 15 && rg == 15) {
            PH[(size_t)N_ROWS * N_HID] = runh;
            PL[(size_t)N_ROWS * N_HID] = totl - runl;
        }
        if (ft == 0) {
            float offZ = 0.f, offG = 0.f, totG = 0.f;
#pragma unroll
            for (int c = 0; c < 16; c++) {
                float a = sZe[c], b = sZg[c];
                if (c < chunk) { offZ += a; offG += b; }
                totG += b;
            }
            for (int r = 0; r < rg; r++) { offZ += segZ[r]; offG += segG[r]; }
            float* ZH = Zhi1 + (size_t)h * PS;
            float* ZL = Zlo1 + (size_t)h * PS;
            float runZ = offZ, runG = offG;
#pragma unroll
            for (int j = 0; j < 16; j++) {
                ZH[k0 + j] = runZ;
                ZL[k0 + j] = totG - runG;
                runZ += sew[rg * 16 + j];
                runG += sgw[rg * 16 + j];
            }
            if (chunk == 15 && rg == 15) { ZH[N_ROWS] = runZ; ZL[N_ROWS] = 0.f; }
        }
    }
    gbar();

    // ---- Phase B1: combine1 -> xc ----
    {
        float* ss = (float*)sm;
        const float* sb = sorted1 + (size_t)h * N_ROWS;
        *reinterpret_cast<float4*>(ss + t * 4) = *reinterpret_cast<const float4*>(sb + t * 4);
        __syncthreads();
        int warp = t >> 5, lane = t & 31;
        const float* ZH = Zhi1 + (size_t)h * PS;
        const float* ZL = Zlo1 + (size_t)h * PS;
        const float* PHb = Phi1 + (size_t)h * KR * N_HID;
        const float* PLb = Plo1 + (size_t)h * KR * N_HID;
        int i0 = chunk * 256;
#pragma unroll
        for (int rr = 0; rr < 8; rr++) {
            int i = i0 + warp * 8 + rr;
            float s = ssrc1[(size_t)h * N_ROWS + i];
            float thr = -s;
            int lo = 0, hi = N_ROWS;
            while (lo < hi) {
                int mid = (lo + hi) >> 1;
                if (ss[mid] >= thr) lo = mid + 1; else hi = mid;
            }
            int k = lo;
            float rho = expf(-0.8f * (s + M1));
            float den = (k == 0) ? ZL[0] : (ZH[k] + rho * ZL[k]);
            float inv = 1.f / den;
            const float* ph = PHb + (size_t)k * N_HID;
            const float* pl = PLb + (size_t)k * N_HID;
#pragma unroll
            for (int u = 0; u < 2; u++) {
                int f = lane + 32 * u;
                float num = (k == 0) ? pl[f] : (ph[f] + rho * pl[f]);
                float feat = num * inv;
                float v = feat > 0.f ? feat : expm1f(feat);
                xc[(size_t)i * N_FEAT + h * N_HID + f] = v;
            }
        }
    }
    gbar();

    // ======== LAYER 2 tail ========
    // ---- Phase G: gemm2 + fused scores2 ----
    {
        float (*xs)[64] = (float(*)[64])sm;
        float (*ws)[16] = (float(*)[16])(sm + 8192);
        int row0 = blk * 32;
        int ir = t >> 4, fc = t & 15;
        float acc = 0.f;
        for (int k0 = 0; k0 < N_FEAT; k0 += 64) {
            __syncthreads();
#pragma unroll
            for (int rep = 0; rep < 2; rep++) {
                int t2 = t + rep * 1024;
                int r = t2 >> 6, kk = t2 & 63;
                xs[r][kk] = xc[(size_t)(row0 + r) * N_FEAT + k0 + kk];
            }
            {
                int kk = t >> 4, f = t & 15;
                if (kk < 64) ws[kk][f] = Wo[(size_t)(k0 + kk) * N_CLASS + f];
            }
            __syncthreads();
            if (t < 512) {
#pragma unroll
                for (int kk = 0; kk < 64; kk++) acc += xs[ir][kk] * ws[kk][fc];
            }
        }
        if (t < 512) {
            h2[(size_t)(row0 + ir) * N_CLASS + fc] = acc;
            float ps = acc * ao[fc];
            float pd = acc * ao[N_CLASS + fc];
#pragma unroll
            for (int off = 1; off < 16; off <<= 1) {
                ps += __shfl_xor_sync(0xffffffffu, ps, off);
                pd += __shfl_xor_sync(0xffffffffu, pd, off);
            }
            if (fc == 0) {
                ssrc2[row0 + ir] = ps;
                sdst2[row0 + ir] = pd;
            }
        }
    }
    gbar();

    if (blk < 8) sortchunk_body(0, blk, sdst2, csort2, (float*)sm);
    gbar();
    if (blk < 8) rank_body(0, blk, sdst2, csort2, sorted2, idx2,
                           (float*)sm, (int*)(sm + 16384));
    gbar();

    float M2 = sorted2[0];

    // ---- Phase A2 ----
    if (blk < 16) {
        int chunk2 = blk;
        int* sidx = (int*)sm;
        float* sew = (float*)(sm + 1024);
        float* sgw = (float*)(sm + 2048);
        float (*sH)[N_CLASS] = (float(*)[N_CLASS])(sm + 3072);
        float (*sL)[N_CLASS] = (float(*)[N_CLASS])(sm + 7168);
        if (t < 256) {
            int base = chunk2 * 256 + t;
            sidx[t] = idx2[base];
            float v = sorted2[base] - M2;
            sew[t] = expf(v); sgw[t] = expf(0.2f * v);
        }
        __syncthreads();
        int ft = t & 15, rg = t >> 4;
        const float* hb = h2 + ft;
        float a = 0.f, b = 0.f;
#pragma unroll
        for (int j = 0; j < 4; j++) {
            int rl = rg * 4 + j;
            float v = hb[(size_t)sidx[rl] * N_CLASS];
            a += v * sew[rl];
            b += v * sgw[rl];
        }
        sH[rg][ft] = a; sL[rg][ft] = b;
        __syncthreads();
        if (t < 16) {
            float sa = 0.f, sb = 0.f;
#pragma unroll
            for (int r = 0; r < 64; r++) { sa += sH[r][t]; sb += sL[r][t]; }
            Chi2[t * 16 + chunk2] = sa;
            Clo2[t * 16 + chunk2] = sb;
        }
        if (t < 32) {
            float za = 0.f, zb = 0.f;
#pragma unroll
            for (int i = 0; i < 8; i++) { za += sew[t + i * 32]; zb += sgw[t + i * 32]; }
#pragma unroll
            for (int off = 16; off; off >>= 1) {
                za += __shfl_xor_sync(0xffffffffu, za, off);
                zb += __shfl_xor_sync(0xffffffffu, zb, off);
            }
            if (t == 0) { Ze2[chunk2] = za; Zg2[chunk2] = zb; }
        }
    }
    gbar();

    // ---- Phase C2 ----
    if (blk < 16) {
        int chunk2 = blk;
        int* sidx = (int*)sm;
        float* sew = (float*)(sm + 1024);
        float* sgw = (float*)(sm + 2048);
        float (*sH)[N_CLASS] = (float(*)[N_CLASS])(sm + 3072);
        float (*sL)[N_CLASS] = (float(*)[N_CLASS])(sm + 7168);
        float* sChi = (float*)(sm + 11264);
        float* sClo = (float*)(sm + 12288);
        float* sZe = (float*)(sm + 13312);
        float* sZg = (float*)(sm + 13376);
        float* segZ = (float*)(sm + 13440);
        float* segG = (float*)(sm + 13696);
        if (t < 256) {
            int base = chunk2 * 256 + t;
            sidx[t] = idx2[base];
            float v = sorted2[base] - M2;
            sew[t] = expf(v); sgw[t] = expf(0.2f * v);
            sChi[t] = Chi2[t]; sClo[t] = Clo2[t];
        }
        if (t < 16) { sZe[t] = Ze2[t]; sZg[t] = Zg2[t]; }
        __syncthreads();
        int ft = t & 15, rg = t >> 4;
        const float* hb = h2 + ft;
        float vh[4], vl[4];
        float a = 0.f, b = 0.f;
#pragma unroll
        for (int j = 0; j < 4; j++) {
            int rl = rg * 4 + j;
            float v = hb[(size_t)sidx[rl] * N_CLASS];
            vh[j] = v * sew[rl];
            vl[j] = v * sgw[rl];
            a += vh[j]; b += vl[j];
        }
        sH[rg][ft] = a; sL[rg][ft] = b;
        if (ft == 0) {
            float sz = 0.f, sg_ = 0.f;
#pragma unroll
            for (int j = 0; j < 4; j++) { sz += sew[rg * 4 + j]; sg_ += sgw[rg * 4 + j]; }
            segZ[rg] = sz; segG[rg] = sg_;
        }
        __syncthreads();
        float offh = 0.f, offl = 0.f, totl = 0.f;
#pragma unroll
        for (int c = 0; c < 16; c++) {
            float ca = sChi[ft * 16 + c], cb = sClo[ft * 16 + c];
            if (c < chunk2) { offh += ca; offl += cb; }
            totl += cb;
        }
        for (int r = 0; r < rg; r++) { offh += sH[r][ft]; offl += sL[r][ft]; }
        float runh = offh, runl = offl;
        int k0 = chunk2 * 256 + rg * 4;
#pragma unroll
        for (int j = 0; j < 4; j++) {
            Phi2[(size_t)(k0 + j) * N_CLASS + ft] = runh;
            Plo2[(size_t)(k0 + j) * N_CLASS + ft] = totl - runl;
            runh += vh[j];
            runl += vl[j];
        }
        if (chunk2 == 15 && rg == 63) {
            Phi2[(size_t)N_ROWS * N_CLASS + ft] = runh;
            Plo2[(size_t)N_ROWS * N_CLASS + ft] = totl - runl;
        }
        if (ft == 0) {
            float offZ = 0.f, offG = 0.f, totG = 0.f;
#pragma unroll
            for (int c = 0; c < 16; c++) {
                float ca = sZe[c], cb = sZg[c];
                if (c < chunk2) { offZ += ca; offG += cb; }
                totG += cb;
            }
            for (int r = 0; r < rg; r++) { offZ += segZ[r]; offG += segG[r]; }
            float runZ = offZ, runG = offG;
#pragma unroll
            for (int j = 0; j < 4; j++) {
                Zhi2[k0 + j] = runZ;
                Zlo2[k0 + j] = totG - runG;
                runZ += sew[rg * 4 + j];
                runG += sgw[rg * 4 + j];
            }
            if (chunk2 == 15 && rg == 63) { Zhi2[N_ROWS] = runZ; Zlo2[N_ROWS] = 0.f; }
        }
    }
    gbar();

    // ---- Phase B2 ----
    if (blk < 64) {
        float* ss = (float*)sm;
        *reinterpret_cast<float4*>(ss + t * 4) = *reinterpret_cast<const float4*>(sorted2 + t * 4);
        __syncthreads();
        int f = t & 15, il = t >> 4;
        int i = blk * 64 + il;
        float s = ssrc2[i];
        float thr = -s;
        int lo = 0, hi = N_ROWS;
        while (lo < hi) {
            int mid = (lo + hi) >> 1;
            if (ss[mid] >= thr) lo = mid + 1; else hi = mid;
        }
        int k = lo;
        float rho = expf(-0.8f * (s + M2));
        float den = (k == 0) ? Zlo2[0] : (Zhi2[k] + rho * Zlo2[k]);
        float num = (k == 0) ? Plo2[f]
                             : (Phi2[(size_t)k * N_CLASS + f] + rho * Plo2[(size_t)k * N_CLASS + f]);
        float feat = num / den;
        float v = feat > 0.f ? feat : expm1f(feat);
        float m = v;
#pragma unroll
        for (int off = 8; off; off >>= 1) m = fmaxf(m, __shfl_xor_sync(0xffffffffu, m, off));
        float ex = expf(v - m);
        float ssum = ex;
#pragma unroll
        for (int off = 8; off; off >>= 1) ssum += __shfl_xor_sync(0xffffffffu, ssum, off);
        out[(size_t)i * N_CLASS + f] = v - m - logf(ssum);
    }
}

// ---------------- launch ----------------
extern "C" void kernel_launch(void* const* d_in, const int* in_sizes, int n_in,
                              void* d_out, int out_size)
{
    const float* x  = (const float*)d_in[0];
    const float* Wh = (const float*)d_in[1];
    const float* ah = (const float*)d_in[2];
    const float* Wo = (const float*)d_in[3];
    const float* ao = (const float*)d_in[4];
    float* out = (float*)d_out;

    float *p_h1, *p_ssrc1, *p_sdst1, *p_csort1, *p_sorted1, *p_Zhi1, *p_Zlo1, *p_Ze1, *p_Zg1;
    float *p_Chi1, *p_Clo1, *p_Phi1, *p_Plo1, *p_xc;
    int *p_idx1;
    float *p_h2, *p_ssrc2, *p_sdst2, *p_csort2, *p_sorted2, *p_Zhi2, *p_Zlo2, *p_Ze2, *p_Zg2;
    float *p_Chi2, *p_Clo2, *p_Phi2, *p_Plo2;
    int *p_idx2;

    cudaGetSymbolAddress((void**)&p_h1, g_h1);
    cudaGetSymbolAddress((void**)&p_ssrc1, g_ssrc1);
    cudaGetSymbolAddress((void**)&p_sdst1, g_sdst1);
    cudaGetSymbolAddress((void**)&p_csort1, g_csort1);
    cudaGetSymbolAddress((void**)&p_sorted1, g_sorted1);
    cudaGetSymbolAddress((void**)&p_idx1, g_idx1);
    cudaGetSymbolAddress((void**)&p_Zhi1, g_Zhi1);
    cudaGetSymbolAddress((void**)&p_Zlo1, g_Zlo1);
    cudaGetSymbolAddress((void**)&p_Ze1, g_Ze1);
    cudaGetSymbolAddress((void**)&p_Zg1, g_Zg1);
    cudaGetSymbolAddress((void**)&p_Chi1, g_Chi1);
    cudaGetSymbolAddress((void**)&p_Clo1, g_Clo1);
    cudaGetSymbolAddress((void**)&p_Phi1, g_Phi1);
    cudaGetSymbolAddress((void**)&p_Plo1, g_Plo1);
    cudaGetSymbolAddress((void**)&p_xc, g_xc);
    cudaGetSymbolAddress((void**)&p_h2, g_h2);
    cudaGetSymbolAddress((void**)&p_ssrc2, g_ssrc2);
    cudaGetSymbolAddress((void**)&p_sdst2, g_sdst2);
    cudaGetSymbolAddress((void**)&p_csort2, g_csort2);
    cudaGetSymbolAddress((void**)&p_sorted2, g_sorted2);
    cudaGetSymbolAddress((void**)&p_idx2, g_idx2);
    cudaGetSymbolAddress((void**)&p_Zhi2, g_Zhi2);
    cudaGetSymbolAddress((void**)&p_Zlo2, g_Zlo2);
    cudaGetSymbolAddress((void**)&p_Ze2, g_Ze2);
    cudaGetSymbolAddress((void**)&p_Zg2, g_Zg2);
    cudaGetSymbolAddress((void**)&p_Chi2, g_Chi2);
    cudaGetSymbolAddress((void**)&p_Clo2, g_Clo2);
    cudaGetSymbolAddress((void**)&p_Phi2, g_Phi2);
    cudaGetSymbolAddress((void**)&p_Plo2, g_Plo2);

    gemm1_mma_kernel<<<dim3(N_ROWS / 128, N_HEADS), 256>>>(x, Wh, ah,
                                                           p_h1, p_ssrc1, p_sdst1);
    megaAll_kernel<<<NB, 1024>>>(p_sdst1, p_csort1, p_sorted1, p_idx1,
                                 p_Zhi1, p_Zlo1, p_Ze1, p_Zg1,
                                 p_h1, p_Chi1, p_Clo1, p_Phi1, p_Plo1, p_ssrc1, p_xc,
                                 Wo, ao, p_h2, p_ssrc2, p_sdst2,
                                 p_csort2, p_sorted2, p_idx2,
                                 p_Zhi2, p_Zlo2, p_Ze2, p_Zg2,
                                 p_Chi2, p_Clo2, p_Phi2, p_Plo2, out);

    (void)in_sizes; (void)n_in; (void)out_size;
}